// round 15
// baseline (speedup 1.0000x reference)
#include <cuda_runtime.h>
#include <cuda.h>
#include <cstdint>

// LIF layer scan: B=64, F=256, L=2048.  out = [z | s], each B*F*L float32.
//
// R15: CHUNK=128 with merged input/z buffer (scan overwrites input in place),
// doubling DRAM write contiguity to 512B per row per store round.
//   grid=148 (1 CTA/SM), 160 threads: tid 0..127 scan (H=111/110), tid 128 TMA.
//   2 merged in/z stages + 2 s slots (4 x 57344B = 230400B SMEM).
// TMA thread per iter: wait_group 0 (drain group k-1) -> reload stage si^1
// with chunk k+1 (load runs ahead of next store burst) -> wait DONE -> store
// z (from in/z stage) + s (from s slot), commit.
// Balanced rows 111/110; dual tensor maps; SW128 tiles 1024-aligned so the
// hardware swizzle matches the in-kernel quad^(r&7) formula.

#define BB 64
#define FF 256
#define LL 2048
#define CHUNK 128
#define NTH 160
#define NCH (LL / CHUNK)     // 16
#define NBIG 104

#define BETA 15.0f
#define DT 1.0f

#define TILE_STRIDE 14336                  // 111*128 padded to 14*1024
#define SET4 (4 * TILE_STRIDE)             // 57344: 4 half-tiles (one chunk)
#define B_IZF(s)  ((s) * 8)                // in/z stage loaded (tx)
#define B_DONE(s) (16 + (s) * 8)           // scan finished chunk in stage s
#define B_SFR(s)  (32 + (s) * 8)           // s slot drained (count=1, pre-armed)
#define IZ_OFF  1024
#define S_OFF   (IZ_OFF + 2 * SET4)        // 115712
#define SMEM_BYTES (S_OFF + 2 * SET4)      // 230400

__device__ __forceinline__ void mbar_init(uint32_t a, uint32_t c) {
    asm volatile("mbarrier.init.shared.b64 [%0], %1;" :: "r"(a), "r"(c) : "memory");
}
__device__ __forceinline__ void mbar_arrive(uint32_t a) {
    asm volatile("mbarrier.arrive.release.cta.shared::cta.b64 _, [%0];"
                 :: "r"(a) : "memory");
}
__device__ __forceinline__ void mbar_expect_tx(uint32_t a, uint32_t bytes) {
    asm volatile("mbarrier.arrive.expect_tx.shared.b64 _, [%0], %1;"
                 :: "r"(a), "r"(bytes) : "memory");
}
__device__ __forceinline__ void mbar_wait(uint32_t a, uint32_t parity) {
    asm volatile(
        "{\n\t.reg .pred P;\n\t"
        "WL_%=:\n\t"
        "mbarrier.try_wait.parity.acquire.cta.shared::cta.b64 P, [%0], %1, 0x989680;\n\t"
        "@P bra.uni WD_%=;\n\t"
        "bra.uni WL_%=;\n\t"
        "WD_%=:\n\t}"
        :: "r"(a), "r"(parity) : "memory");
}
__device__ __forceinline__ void tma_load_2d(uint32_t smem, const CUtensorMap* m,
                                            int x, int y, uint32_t bar) {
    asm volatile(
        "cp.async.bulk.tensor.2d.shared::cta.global.tile.mbarrier::complete_tx::bytes "
        "[%0], [%1, {%2, %3}], [%4];"
        :: "r"(smem), "l"(m), "r"(x), "r"(y), "r"(bar) : "memory");
}
__device__ __forceinline__ void tma_store_2d(const CUtensorMap* m,
                                             int x, int y, uint32_t smem) {
    asm volatile(
        "cp.async.bulk.tensor.2d.global.shared::cta.tile.bulk_group "
        "[%0, {%1, %2}], [%3];"
        :: "l"(m), "r"(x), "r"(y), "r"(smem) : "memory");
}

__global__ __launch_bounds__(NTH, 1)
void lif_tma_kernel(const __grid_constant__ CUtensorMap tin_a,
                    const __grid_constant__ CUtensorMap tin_b,
                    const __grid_constant__ CUtensorMap tz_a,
                    const __grid_constant__ CUtensorMap tz_b,
                    const __grid_constant__ CUtensorMap ts_a,
                    const __grid_constant__ CUtensorMap ts_b,
                    const float* __restrict__ raw_tau,
                    const float* __restrict__ thr_p)
{
    extern __shared__ char smem[];
    uint32_t sb;
    asm("{ .reg .u64 t; cvta.to.shared.u64 t, %1; cvt.u32.u64 %0, t; }"
        : "=r"(sb) : "l"(smem));

    const int tid = threadIdx.x;
    const int bid = blockIdx.x;
    const bool big = (bid < NBIG);
    const int H = big ? 111 : 110;
    const int row0 = big ? bid * 111 : NBIG * 111 + (bid - NBIG) * 110;
    const CUtensorMap* tin = big ? &tin_a : &tin_b;
    const CUtensorMap* tz  = big ? &tz_a  : &tz_b;
    const CUtensorMap* tsm = big ? &ts_a  : &ts_b;
    const uint32_t tx_bytes = (uint32_t)H * 512;   // 4 half-tiles x H x 128B

    if (tid == 0) {
        #pragma unroll
        for (int s = 0; s < 2; s++) {
            mbar_init(sb + B_IZF(s), 1);
            mbar_init(sb + B_DONE(s), 128);
            mbar_init(sb + B_SFR(s), 1);
        }
    }
    __syncthreads();   // barrier init visible; only block-wide sync in kernel

    if (tid < 128) {
        // ===================== scan threads =====================
        const float thr = thr_p[0];
        const bool active = (tid < H);
        float alpha = 0.0f, one_m_alpha = 0.0f;
        if (active) {
            float rt = raw_tau[(row0 + tid) % FF];
            float sp = fmaxf(rt, 0.0f) + log1pf(expf(-fabsf(rt)));
            float tau = sp + 1e-4f;
            alpha = expf(-DT / tau);
            one_m_alpha = 1.0f - alpha;
        }
        const float beta_thr = BETA * thr;
        const int sw = tid & 7;
        const uint32_t rbase = (uint32_t)tid * 128;
        float vv = 0.0f;

        for (int k = 0; k < NCH; k++) {
            const int si = k & 1;
            const uint32_t par = (k >> 1) & 1;
            mbar_wait(sb + B_IZF(si), par);   // input loaded (implies prior z drained)
            mbar_wait(sb + B_SFR(si), par);   // s slot drained (pre-armed)

            if (active) {
                char* izb = smem + IZ_OFF + si * SET4 + rbase;   // input, then z
                char* st  = smem + S_OFF  + si * SET4 + rbase;   // s tiles
                #pragma unroll
                for (int tb = 0; tb < 32; tb++) {
                    const uint32_t off = (uint32_t)(tb >> 3) * TILE_STRIDE
                                       + ((uint32_t)((tb & 7) ^ sw) << 4);
                    float4 in4 = *(const float4*)(izb + off);     // LDS.128
                    float4 z4, s4;
                    float v_pre; bool spk;
                    v_pre = fmaf(alpha, vv, one_m_alpha * in4.x);
                    z4.x = fmaf(BETA, v_pre, -beta_thr);
                    spk = (v_pre >= thr); s4.x = spk ? 1.0f : 0.0f; vv = spk ? 0.0f : v_pre;
                    v_pre = fmaf(alpha, vv, one_m_alpha * in4.y);
                    z4.y = fmaf(BETA, v_pre, -beta_thr);
                    spk = (v_pre >= thr); s4.y = spk ? 1.0f : 0.0f; vv = spk ? 0.0f : v_pre;
                    v_pre = fmaf(alpha, vv, one_m_alpha * in4.z);
                    z4.z = fmaf(BETA, v_pre, -beta_thr);
                    spk = (v_pre >= thr); s4.z = spk ? 1.0f : 0.0f; vv = spk ? 0.0f : v_pre;
                    v_pre = fmaf(alpha, vv, one_m_alpha * in4.w);
                    z4.w = fmaf(BETA, v_pre, -beta_thr);
                    spk = (v_pre >= thr); s4.w = spk ? 1.0f : 0.0f; vv = spk ? 0.0f : v_pre;
                    *(float4*)(izb + off) = z4;                   // overwrite in place
                    *(float4*)(st  + off) = s4;
                }
            }
            mbar_arrive(sb + B_DONE(si));     // z + s tiles ready
        }
    } else if (tid == 128) {
        // ===================== TMA-issue thread =====================
        mbar_arrive(sb + B_SFR(0));           // pre-arm: s slots start empty
        mbar_arrive(sb + B_SFR(1));
        // prologue: load chunks 0,1 into stages 0,1
        #pragma unroll
        for (int s = 0; s < 2; s++) {
            mbar_expect_tx(sb + B_IZF(s), tx_bytes);
            const uint32_t dst = sb + IZ_OFF + s * SET4;
            #pragma unroll
            for (int c = 0; c < 4; c++)
                tma_load_2d(dst + c * TILE_STRIDE, tin, s * CHUNK + c * 32, row0,
                            sb + B_IZF(s));
        }

        for (int k = 0; k < NCH; k++) {
            const int si = k & 1;
            const uint32_t par = (k >> 1) & 1;
            if (k >= 1) {
                // drain group k-1 fully: frees in/z stage si^1 and s slot si^1
                asm volatile("cp.async.bulk.wait_group 0;" ::: "memory");
                mbar_arrive(sb + B_SFR(si ^ 1));
                if (k + 1 < NCH) {
                    // reload stage si^1 with chunk k+1 (ahead of next store burst)
                    mbar_expect_tx(sb + B_IZF(si ^ 1), tx_bytes);
                    const uint32_t dst = sb + IZ_OFF + (si ^ 1) * SET4;
                    #pragma unroll
                    for (int c = 0; c < 4; c++)
                        tma_load_2d(dst + c * TILE_STRIDE, tin,
                                    (k + 1) * CHUNK + c * 32, row0,
                                    sb + B_IZF(si ^ 1));
                }
            }
            // store chunk k: z from in/z stage si, s from slot si
            mbar_wait(sb + B_DONE(si), par);
            asm volatile("fence.proxy.async.shared::cta;" ::: "memory");
            const int t0 = k * CHUNK;
            const uint32_t izb = sb + IZ_OFF + si * SET4;
            const uint32_t stb = sb + S_OFF  + si * SET4;
            #pragma unroll
            for (int c = 0; c < 4; c++) {
                tma_store_2d(tz,  t0 + c * 32, row0, izb + c * TILE_STRIDE);
                tma_store_2d(tsm, t0 + c * 32, row0, stb + c * TILE_STRIDE);
            }
            asm volatile("cp.async.bulk.commit_group;" ::: "memory");
        }
        asm volatile("cp.async.bulk.wait_group 0;" ::: "memory");
    }
}

// ---------------- host side ----------------

typedef CUresult (*EncodeFn)(CUtensorMap*, CUtensorMapDataType, cuuint32_t, void*,
                             const cuuint64_t*, const cuuint64_t*,
                             const cuuint32_t*, const cuuint32_t*,
                             CUtensorMapInterleave, CUtensorMapSwizzle,
                             CUtensorMapL2promotion, CUtensorMapFloatOOBfill);

static void make_map(EncodeFn enc, CUtensorMap* m, void* base, unsigned H) {
    cuuint64_t dims[2]    = {LL, (cuuint64_t)BB * FF};
    cuuint64_t strides[1] = {LL * sizeof(float)};
    cuuint32_t box[2]     = {32, H};
    cuuint32_t es[2]      = {1, 1};
    enc(m, CU_TENSOR_MAP_DATA_TYPE_FLOAT32, 2, base, dims, strides, box, es,
        CU_TENSOR_MAP_INTERLEAVE_NONE, CU_TENSOR_MAP_SWIZZLE_128B,
        CU_TENSOR_MAP_L2_PROMOTION_L2_128B, CU_TENSOR_MAP_FLOAT_OOB_FILL_NONE);
}

extern "C" void kernel_launch(void* const* d_in, const int* in_sizes, int n_in,
                              void* d_out, int out_size)
{
    float* I             = (float*)d_in[0];
    const float* raw_tau = (const float*)d_in[1];
    const float* thr     = (const float*)d_in[2];
    float* out           = (float*)d_out;

    static EncodeFn enc = nullptr;
    if (!enc) {
        cudaDriverEntryPointQueryResult qr;
        void* fp = nullptr;
        cudaGetDriverEntryPoint("cuTensorMapEncodeTiled", &fp,
                                cudaEnableDefault, &qr);
        enc = (EncodeFn)fp;
        cudaFuncSetAttribute(lif_tma_kernel,
                             cudaFuncAttributeMaxDynamicSharedMemorySize, SMEM_BYTES);
    }
    if (!enc) return;

    float* sbase = out + (size_t)BB * FF * LL;
    CUtensorMap in_a, in_b, z_a, z_b, s_a, s_b;
    make_map(enc, &in_a, I, 111);     make_map(enc, &in_b, I, 110);
    make_map(enc, &z_a,  out, 111);   make_map(enc, &z_b,  out, 110);
    make_map(enc, &s_a,  sbase, 111); make_map(enc, &s_b,  sbase, 110);

    lif_tma_kernel<<<148, NTH, SMEM_BYTES>>>(in_a, in_b, z_a, z_b, s_a, s_b,
                                             raw_tau, thr);
}

// round 16
// speedup vs baseline: 1.0778x; 1.0778x over previous
#include <cuda_runtime.h>
#include <cuda.h>
#include <cstdint>

// LIF layer scan: B=64, F=256, L=2048.  out = [z | s], each B*F*L float32.
//
// R16: balanced 2 CTAs/SM TMA pipeline (grid=296, 96 threads):
//   tid 0..63 : scan threads (H=56/55 active), one row each
//   tid 64    : TMA-issue thread
// 104 CTAs own 56 rows, 192 own 55 (104*56+192*55=16384). Two CTAs per SM give
// two independent TMA command streams and 2x outstanding transactions per SM.
// TILE_STRIDE = 56*128 = 7168 = 7*1024: tiles naturally 1024-aligned, so the
// SW128 hardware swizzle matches the in-kernel quad^(r&7) formula.
// Handshakes as R12: IN_FULL (tx), IN_EMPTY / ST_FULL (count=64),
// ST_FREE (count=1, pre-armed). Input ring 2 stages, store ring 2 slots.

#define BB 64
#define FF 256
#define LL 2048
#define CHUNK 64
#define NTH 96
#define NCH (LL / CHUNK)     // 32
#define NBIG 104             // CTAs with 56 rows; rest have 55

#define BETA 15.0f
#define DT 1.0f

#define TILE_STRIDE 7168                   // 56*128, already 1024-aligned
#define IN_STG  (2 * TILE_STRIDE)          // 14336 per input stage
#define ST_SLOT (4 * TILE_STRIDE)          // 28672 per store slot
#define B_INF(s)  ((s) * 8)                // IN_FULL
#define B_INE(s)  (16 + (s) * 8)           // IN_EMPTY
#define B_STF(s)  (32 + (s) * 8)           // ST_FULL
#define B_STE(s)  (48 + (s) * 8)           // ST_FREE
#define IN_OFF  1024
#define ST_OFF  (IN_OFF + 2 * IN_STG)       // 29696 (1024-aligned)
#define SMEM_BYTES (ST_OFF + 2 * ST_SLOT)   // 87040  -> 2 CTAs/SM

__device__ __forceinline__ void mbar_init(uint32_t a, uint32_t c) {
    asm volatile("mbarrier.init.shared.b64 [%0], %1;" :: "r"(a), "r"(c) : "memory");
}
__device__ __forceinline__ void mbar_arrive(uint32_t a) {
    asm volatile("mbarrier.arrive.release.cta.shared::cta.b64 _, [%0];"
                 :: "r"(a) : "memory");
}
__device__ __forceinline__ void mbar_expect_tx(uint32_t a, uint32_t bytes) {
    asm volatile("mbarrier.arrive.expect_tx.shared.b64 _, [%0], %1;"
                 :: "r"(a), "r"(bytes) : "memory");
}
__device__ __forceinline__ void mbar_wait(uint32_t a, uint32_t parity) {
    asm volatile(
        "{\n\t.reg .pred P;\n\t"
        "WL_%=:\n\t"
        "mbarrier.try_wait.parity.acquire.cta.shared::cta.b64 P, [%0], %1, 0x989680;\n\t"
        "@P bra.uni WD_%=;\n\t"
        "bra.uni WL_%=;\n\t"
        "WD_%=:\n\t}"
        :: "r"(a), "r"(parity) : "memory");
}
__device__ __forceinline__ void tma_load_2d(uint32_t smem, const CUtensorMap* m,
                                            int x, int y, uint32_t bar) {
    asm volatile(
        "cp.async.bulk.tensor.2d.shared::cta.global.tile.mbarrier::complete_tx::bytes "
        "[%0], [%1, {%2, %3}], [%4];"
        :: "r"(smem), "l"(m), "r"(x), "r"(y), "r"(bar) : "memory");
}
__device__ __forceinline__ void tma_store_2d(const CUtensorMap* m,
                                             int x, int y, uint32_t smem) {
    asm volatile(
        "cp.async.bulk.tensor.2d.global.shared::cta.tile.bulk_group "
        "[%0, {%1, %2}], [%3];"
        :: "l"(m), "r"(x), "r"(y), "r"(smem) : "memory");
}

__global__ __launch_bounds__(NTH, 2)
void lif_tma_kernel(const __grid_constant__ CUtensorMap tin_a,
                    const __grid_constant__ CUtensorMap tin_b,
                    const __grid_constant__ CUtensorMap tz_a,
                    const __grid_constant__ CUtensorMap tz_b,
                    const __grid_constant__ CUtensorMap ts_a,
                    const __grid_constant__ CUtensorMap ts_b,
                    const float* __restrict__ raw_tau,
                    const float* __restrict__ thr_p)
{
    extern __shared__ char smem[];
    uint32_t sb;
    asm("{ .reg .u64 t; cvta.to.shared.u64 t, %1; cvt.u32.u64 %0, t; }"
        : "=r"(sb) : "l"(smem));

    const int tid = threadIdx.x;
    const int bid = blockIdx.x;
    const bool big = (bid < NBIG);
    const int H = big ? 56 : 55;
    const int row0 = big ? bid * 56 : NBIG * 56 + (bid - NBIG) * 55;
    const CUtensorMap* tin = big ? &tin_a : &tin_b;
    const CUtensorMap* tz  = big ? &tz_a  : &tz_b;
    const CUtensorMap* tsm = big ? &ts_a  : &ts_b;
    const uint32_t tx_bytes = (uint32_t)H * 256;   // 2 half-tiles x H x 128B

    if (tid == 0) {
        #pragma unroll
        for (int s = 0; s < 2; s++) {
            mbar_init(sb + B_INF(s), 1);
            mbar_init(sb + B_INE(s), 64);
            mbar_init(sb + B_STF(s), 64);
            mbar_init(sb + B_STE(s), 1);
        }
    }
    __syncthreads();   // barrier init visible; only block-wide sync in kernel

    if (tid < 64) {
        // ===================== scan threads =====================
        const float thr = thr_p[0];
        const bool active = (tid < H);
        float alpha = 0.0f, one_m_alpha = 0.0f;
        if (active) {
            float rt = raw_tau[(row0 + tid) % FF];
            float sp = fmaxf(rt, 0.0f) + log1pf(expf(-fabsf(rt)));
            float tau = sp + 1e-4f;
            alpha = expf(-DT / tau);
            one_m_alpha = 1.0f - alpha;
        }
        const float beta_thr = BETA * thr;
        const int sw = tid & 7;
        const uint32_t rbase = (uint32_t)tid * 128;
        float vv = 0.0f;

        for (int k = 0; k < NCH; k++) {
            const int si = k & 1;
            const uint32_t par = (k >> 1) & 1;
            mbar_wait(sb + B_INF(si), par);   // input stage ready
            mbar_wait(sb + B_STE(si), par);   // store slot drained (pre-armed)

            if (active) {
                const char* ib = smem + IN_OFF + si * IN_STG + rbase;
                char* zt = smem + ST_OFF + si * ST_SLOT + rbase;
                char* st = zt + 2 * TILE_STRIDE;
                #pragma unroll
                for (int tb = 0; tb < 16; tb++) {
                    const uint32_t off = (uint32_t)(tb >> 3) * TILE_STRIDE
                                       + ((uint32_t)((tb & 7) ^ sw) << 4);
                    float4 in4 = *(const float4*)(ib + off);     // LDS.128
                    float4 z4, s4;
                    float v_pre; bool spk;
                    v_pre = fmaf(alpha, vv, one_m_alpha * in4.x);
                    z4.x = fmaf(BETA, v_pre, -beta_thr);
                    spk = (v_pre >= thr); s4.x = spk ? 1.0f : 0.0f; vv = spk ? 0.0f : v_pre;
                    v_pre = fmaf(alpha, vv, one_m_alpha * in4.y);
                    z4.y = fmaf(BETA, v_pre, -beta_thr);
                    spk = (v_pre >= thr); s4.y = spk ? 1.0f : 0.0f; vv = spk ? 0.0f : v_pre;
                    v_pre = fmaf(alpha, vv, one_m_alpha * in4.z);
                    z4.z = fmaf(BETA, v_pre, -beta_thr);
                    spk = (v_pre >= thr); s4.z = spk ? 1.0f : 0.0f; vv = spk ? 0.0f : v_pre;
                    v_pre = fmaf(alpha, vv, one_m_alpha * in4.w);
                    z4.w = fmaf(BETA, v_pre, -beta_thr);
                    spk = (v_pre >= thr); s4.w = spk ? 1.0f : 0.0f; vv = spk ? 0.0f : v_pre;
                    *(float4*)(zt + off) = z4;                   // STS.128
                    *(float4*)(st + off) = s4;                   // STS.128
                }
            }
            mbar_arrive(sb + B_INE(si));      // input stage consumed
            mbar_arrive(sb + B_STF(si));      // z/s tiles written
        }
    } else if (tid == 64) {
        // ===================== TMA-issue thread =====================
        mbar_arrive(sb + B_STE(0));           // pre-arm: slots start empty
        mbar_arrive(sb + B_STE(1));
        // prologue: load input stages 0,1
        #pragma unroll
        for (int s = 0; s < 2; s++) {
            mbar_expect_tx(sb + B_INF(s), tx_bytes);
            const uint32_t dst = sb + IN_OFF + s * IN_STG;
            tma_load_2d(dst,               tin, s * CHUNK,      row0, sb + B_INF(s));
            tma_load_2d(dst + TILE_STRIDE, tin, s * CHUNK + 32, row0, sb + B_INF(s));
        }

        for (int k = 0; k < NCH; k++) {
            const int si = k & 1;
            const uint32_t par = (k >> 1) & 1;
            // refill input stage si with chunk k+2
            if (k + 2 < NCH) {
                mbar_wait(sb + B_INE(si), par);
                mbar_expect_tx(sb + B_INF(si), tx_bytes);
                const uint32_t dst = sb + IN_OFF + si * IN_STG;
                tma_load_2d(dst,               tin, (k + 2) * CHUNK,      row0, sb + B_INF(si));
                tma_load_2d(dst + TILE_STRIDE, tin, (k + 2) * CHUNK + 32, row0, sb + B_INF(si));
            }
            // store chunk k from slot si
            mbar_wait(sb + B_STF(si), par);   // tiles written (acquire)
            asm volatile("fence.proxy.async.shared::cta;" ::: "memory");
            const int t0 = k * CHUNK;
            const uint32_t slot = sb + ST_OFF + si * ST_SLOT;
            tma_store_2d(tz,  t0,      row0, slot);
            tma_store_2d(tz,  t0 + 32, row0, slot + TILE_STRIDE);
            tma_store_2d(tsm, t0,      row0, slot + 2 * TILE_STRIDE);
            tma_store_2d(tsm, t0 + 32, row0, slot + 3 * TILE_STRIDE);
            asm volatile("cp.async.bulk.commit_group;" ::: "memory");
            if (k >= 1) {                     // group k-1 drained -> slot free
                asm volatile("cp.async.bulk.wait_group 1;" ::: "memory");
                mbar_arrive(sb + B_STE(si ^ 1));
            }
        }
        asm volatile("cp.async.bulk.wait_group 0;" ::: "memory");
    }
}

// ---------------- host side ----------------

typedef CUresult (*EncodeFn)(CUtensorMap*, CUtensorMapDataType, cuuint32_t, void*,
                             const cuuint64_t*, const cuuint64_t*,
                             const cuuint32_t*, const cuuint32_t*,
                             CUtensorMapInterleave, CUtensorMapSwizzle,
                             CUtensorMapL2promotion, CUtensorMapFloatOOBfill);

static void make_map(EncodeFn enc, CUtensorMap* m, void* base, unsigned H) {
    cuuint64_t dims[2]    = {LL, (cuuint64_t)BB * FF};
    cuuint64_t strides[1] = {LL * sizeof(float)};
    cuuint32_t box[2]     = {32, H};
    cuuint32_t es[2]      = {1, 1};
    enc(m, CU_TENSOR_MAP_DATA_TYPE_FLOAT32, 2, base, dims, strides, box, es,
        CU_TENSOR_MAP_INTERLEAVE_NONE, CU_TENSOR_MAP_SWIZZLE_128B,
        CU_TENSOR_MAP_L2_PROMOTION_L2_128B, CU_TENSOR_MAP_FLOAT_OOB_FILL_NONE);
}

extern "C" void kernel_launch(void* const* d_in, const int* in_sizes, int n_in,
                              void* d_out, int out_size)
{
    float* I             = (float*)d_in[0];
    const float* raw_tau = (const float*)d_in[1];
    const float* thr     = (const float*)d_in[2];
    float* out           = (float*)d_out;

    static EncodeFn enc = nullptr;
    if (!enc) {
        cudaDriverEntryPointQueryResult qr;
        void* fp = nullptr;
        cudaGetDriverEntryPoint("cuTensorMapEncodeTiled", &fp,
                                cudaEnableDefault, &qr);
        enc = (EncodeFn)fp;
        cudaFuncSetAttribute(lif_tma_kernel,
                             cudaFuncAttributeMaxDynamicSharedMemorySize, SMEM_BYTES);
    }
    if (!enc) return;

    float* sbase = out + (size_t)BB * FF * LL;
    CUtensorMap in_a, in_b, z_a, z_b, s_a, s_b;
    make_map(enc, &in_a, I, 56);     make_map(enc, &in_b, I, 55);
    make_map(enc, &z_a,  out, 56);   make_map(enc, &z_b,  out, 55);
    make_map(enc, &s_a,  sbase, 56); make_map(enc, &s_b,  sbase, 55);

    lif_tma_kernel<<<296, NTH, SMEM_BYTES>>>(in_a, in_b, z_a, z_b, s_a, s_b,
                                             raw_tau, thr);
}